// round 8
// baseline (speedup 1.0000x reference)
#include <cuda_runtime.h>
#include <cuda_bf16.h>
#include <math.h>

#define BB 4
#define SS 4096
#define DD 1024
#define HALF (DD/2)
#define TD (3*DD)

// ---------------- scratch (device globals; no allocation allowed) ----------------
__device__ __align__(16) __nv_bfloat16  g_qkvbf[(long long)BB*SS*TD];   // 96MB
__device__ __align__(16) __nv_bfloat16  g_P[(long long)BB*SS*SS];       // 128MB unnormalized 3^s
__device__ __align__(16) __nv_bfloat16  g_hbf[(long long)BB*SS*DD];     // 32MB
__device__ __align__(16) unsigned char  g_qf8[(long long)BB*SS*DD];     // 16MB e4m3
__device__ __align__(16) unsigned char  g_kf8[(long long)BB*SS*DD];     // 16MB e4m3
__device__ __align__(16) __nv_bfloat16  g_vwT[(long long)BB*DD*SS];     // 32MB (V@Wproj)^T [b][d][s]
__device__ __align__(16) __nv_bfloat16  g_wqkvT[(long long)TD*DD];      // 6MB  [n][k]
__device__ __align__(16) __nv_bfloat16  g_wprojT[(long long)DD*DD];     // 2MB  [n][k]
__device__ __align__(16) float          g_scratch[33554432];            // 134MB split-K partials (1024 tiles x 32768)
__device__ int   g_ctr[1024];                                           // split-K arrival counters
__device__ float g_den[(long long)BB*SS];                               // row sums of P
__device__ float g_invf[HALF];
__device__ signed char g_cos[SS*HALF];
__device__ signed char g_sin[SS*HALF];

// ---------------- ternary rope tables ----------------
__global__ void build_inv_kernel() {
    int j = threadIdx.x;
    float e = (float)j / (float)HALF;
    g_invf[j] = 1.0f / (float)pow(10000.0, (double)e);
}
__global__ void build_tables_kernel() {
    int idx = blockIdx.x * blockDim.x + threadIdx.x;
    if (idx >= SS * HALF) return;
    int s = idx / HALF;
    int j = idx - s * HALF;
    float ang = (float)s * g_invf[j];
    double t = (double)ang;
    double k = rint(t * 0.15915494309189535);
    float r = (float)(t - k * 6.283185307179586);
    float c, sn;
    sincosf(r, &sn, &c);
    g_cos[idx] = (signed char)__float2int_rn(c);
    g_sin[idx] = (signed char)__float2int_rn(sn);
}

// ---------------- zero den + counters ----------------
__global__ void zero_kernel(float* __restrict__ den, int* __restrict__ ctr) {
    int i = blockIdx.x * 256 + threadIdx.x;
    if (i < BB * SS) den[i] = 0.0f;
    else ctr[i - BB * SS] = 0;
}

// ---------------- reductions ----------------
__device__ __forceinline__ float block_reduce_sum(float v, float* red) {
    int lane = threadIdx.x & 31, w = threadIdx.x >> 5;
    #pragma unroll
    for (int o = 16; o; o >>= 1) v += __shfl_xor_sync(0xffffffffu, v, o);
    if (lane == 0) red[w] = v;
    __syncthreads();
    if (w == 0) {
        v = (lane < (int)(blockDim.x >> 5)) ? red[lane] : 0.0f;
        #pragma unroll
        for (int o = 16; o; o >>= 1) v += __shfl_xor_sync(0xffffffffu, v, o);
        if (lane == 0) red[0] = v;
    }
    __syncthreads();
    float out = red[0];
    __syncthreads();
    return out;
}

// ---------------- rmsnorm -> bf16 ----------------
__global__ __launch_bounds__(256) void rmsnorm_kernel(const float* __restrict__ x,
                                                      const float* __restrict__ g,
                                                      __nv_bfloat16* __restrict__ h) {
    __shared__ float red[32];
    long long base = (long long)blockIdx.x * DD;
    float4 v = *(const float4*)(x + base + (long long)threadIdx.x * 4);
    float ss = v.x*v.x + v.y*v.y + v.z*v.z + v.w*v.w;
    float total = block_reduce_sum(ss, red);
    float r = rsqrtf(total * (1.0f / DD) + 1e-6f);
    float4 gv = *(const float4*)(g + (long long)threadIdx.x * 4);
    __nv_bfloat162 o0 = {__float2bfloat16(v.x*r*gv.x), __float2bfloat16(v.y*r*gv.y)};
    __nv_bfloat162 o1 = {__float2bfloat16(v.z*r*gv.z), __float2bfloat16(v.w*r*gv.w)};
    __nv_bfloat162* hp = (__nv_bfloat162*)(h + base + (long long)threadIdx.x * 4);
    hp[0] = o0; hp[1] = o1;
}

// ---------------- weight transpose + convert f32 -> bf16 ----------------
__global__ __launch_bounds__(256) void transpose_cvt_kernel(
    const float* __restrict__ in, int ldin,
    __nv_bfloat16* __restrict__ out, int ldout)
{
    __shared__ float tile[32][33];
    int r0 = blockIdx.y * 32, c0 = blockIdx.x * 32;
    int tx = threadIdx.x & 31, ty = threadIdx.x >> 5;
    #pragma unroll
    for (int i = 0; i < 4; i++)
        tile[ty + i * 8][tx] = in[(long long)(r0 + ty + i * 8) * ldin + c0 + tx];
    __syncthreads();
    #pragma unroll
    for (int i = 0; i < 4; i++)
        out[(long long)(c0 + ty + i * 8) * ldout + r0 + tx] = __float2bfloat16(tile[tx][ty + i * 8]);
}

// ---------------- rope: bf16 qkv -> e4m3 q,k ----------------
__device__ __forceinline__ unsigned short cvt_e4m3x2(float lo, float hi) {
    unsigned short r;
    asm("cvt.rn.satfinite.e4m3x2.f32 %0, %1, %2;" : "=h"(r) : "f"(hi), "f"(lo));
    return r;
}
__global__ __launch_bounds__(256) void rope_kernel(const __nv_bfloat16* __restrict__ qkv,
                                                   unsigned short* __restrict__ qo,
                                                   unsigned short* __restrict__ ko) {
    int bs = blockIdx.x;
    int s = bs & (SS - 1);
    int t = threadIdx.x;
    int j0 = 2 * t;
    float c0 = (float)g_cos[s * HALF + j0],     s0 = (float)g_sin[s * HALF + j0];
    float c1 = (float)g_cos[s * HALF + j0 + 1], s1 = (float)g_sin[s * HALF + j0 + 1];
    const __nv_bfloat16* q = qkv + (long long)bs * TD;
    const __nv_bfloat16* k = q + DD;
    long long ob = (long long)bs * (DD / 2);
    #pragma unroll
    for (int w = 0; w < 2; w++) {
        const __nv_bfloat16* src = w ? k : q;
        unsigned short* dst = w ? ko : qo;
        float a0 = __bfloat162float(src[j0]),        a1 = __bfloat162float(src[j0 + 1]);
        float b0 = __bfloat162float(src[j0 + HALF]), b1 = __bfloat162float(src[j0 + HALF + 1]);
        dst[ob + t]            = cvt_e4m3x2(a0 * c0 - b0 * s0, a1 * c1 - b1 * s1);
        dst[ob + t + HALF / 2] = cvt_e4m3x2(b0 * c0 + a0 * s0, b1 * c1 + a1 * s1);
    }
}

// ---------------- mma helpers ----------------
__device__ __forceinline__ void ldsm4(unsigned* r, unsigned addr) {
    asm volatile("ldmatrix.sync.aligned.m8n8.x4.shared.b16 {%0,%1,%2,%3},[%4];"
                 : "=r"(r[0]), "=r"(r[1]), "=r"(r[2]), "=r"(r[3]) : "r"(addr));
}
__device__ __forceinline__ void mma_bf16(float* c, const unsigned* a, unsigned b0, unsigned b1) {
    asm volatile("mma.sync.aligned.m16n8k16.row.col.f32.bf16.bf16.f32 "
                 "{%0,%1,%2,%3},{%4,%5,%6,%7},{%8,%9},{%0,%1,%2,%3};"
                 : "+f"(c[0]), "+f"(c[1]), "+f"(c[2]), "+f"(c[3])
                 : "r"(a[0]), "r"(a[1]), "r"(a[2]), "r"(a[3]), "r"(b0), "r"(b1));
}
__device__ __forceinline__ void mma_e4m3(float* c, const unsigned* a, unsigned b0, unsigned b1) {
    asm volatile("mma.sync.aligned.m16n8k32.row.col.f32.e4m3.e4m3.f32 "
                 "{%0,%1,%2,%3},{%4,%5,%6,%7},{%8,%9},{%0,%1,%2,%3};"
                 : "+f"(c[0]), "+f"(c[1]), "+f"(c[2]), "+f"(c[3])
                 : "r"(a[0]), "r"(a[1]), "r"(a[2]), "r"(a[3]), "r"(b0), "r"(b1));
}
__device__ __forceinline__ void cpasync16(unsigned s, const void* g) {
    asm volatile("cp.async.cg.shared.global [%0], [%1], 16;" :: "r"(s), "l"(g));
}
#define CP_COMMIT() asm volatile("cp.async.commit_group;" ::: "memory")

__device__ __forceinline__ unsigned swz(int row, int ch) {
    int o = row * 128 + ch * 16;
    return (unsigned)(o ^ ((o >> 3) & 0x70));
}

// ================= persistent TN GEMM: tile 128x256, 128B k-chunks, optional split-K =================
// EPI: 1 = bf16 out (+bias), 2 = bf16 out = 3^(acc*alpha) + row-sum atomics into dptr,
//      3 = bf16 out plain,   4 = f32 out = acc/dptr[row] + bias + resid
// SPLITK: physical tiles = 2*nt; two CTAs per logical tile; second arriver sums + finishes.
#define STG 49152u
template <int IN8, int EPI, int SPLITK>
__global__ __launch_bounds__(256) void gemm_tc(
    int T, int gx, int gy, int gz,
    const char* __restrict__ A0, long long ldaB, long long sAB,
    const char* __restrict__ B0, long long ldbB, long long sBB,
    void* __restrict__ Cv, int ldc, long long sC,
    float alpha,
    const float* __restrict__ bias,
    const float* __restrict__ resid, long long sR,
    float* __restrict__ dptr, long long sRS,
    float* __restrict__ scratch, int* __restrict__ ctr)
{
    extern __shared__ __align__(1024) char dsm[];
    __shared__ int sOld;
    unsigned sbase = (unsigned)__cvta_generic_to_shared(dsm);

    const int t = threadIdx.x;
    const int G = gridDim.x;
    const int gxy = gx * gy;
    const int ntL = gxy * gz;
    const int ntP = SPLITK ? ntL * 2 : ntL;
    const int myCount = (ntP - (int)blockIdx.x + G - 1) / G;
    if (myCount <= 0) return;
    const int myTotal = myCount * T;

    const int lrow = t >> 3;
    const int lch  = t & 7;
    const int warp = t >> 5;
    const int wm = warp >> 2;
    const int wn = warp & 3;
    const int lane = t & 31;
    const int lrow16 = lane & 15;
    const int lhalf  = lane >> 4;

    float acc[4][8][4];
    #pragma unroll
    for (int i = 0; i < 4; i++)
        #pragma unroll
        for (int j = 0; j < 8; j++)
            #pragma unroll
            for (int v = 0; v < 4; v++) acc[i][j][v] = 0.0f;

    auto prefetchChunk = [&](int j) {
        if (j < myTotal) {
            int i = j / T, c = j - i * T;
            int p = (int)blockIdx.x + i * G;
            int lt = SPLITK ? (p >> 1) : p;
            int hk = SPLITK ? (p & 1) : 0;
            int z2 = lt / gxy; int rr = lt - z2 * gxy;
            int by = rr / gx, bx = rr - by * gx;
            const char* Ap = A0 + z2 * sAB + (long long)(by * 128) * ldaB;
            const char* Bp = B0 + z2 * sBB + (long long)(bx * 256) * ldbB;
            unsigned aB = sbase + (unsigned)(j % 3) * STG;
            unsigned bB = aB + 16384u;
            long long ko = (long long)c * 128 + lch * 16 + (long long)hk * T * 128;
            #pragma unroll
            for (int ii = 0; ii < 4; ii++)
                cpasync16(aB + swz(lrow + ii * 32, lch), Ap + (long long)(lrow + ii * 32) * ldaB + ko);
            #pragma unroll
            for (int ii = 0; ii < 8; ii++)
                cpasync16(bB + swz(lrow + ii * 32, lch), Bp + (long long)(lrow + ii * 32) * ldbB + ko);
        }
        CP_COMMIT();
    };

    prefetchChunk(0);
    prefetchChunk(1);

    for (int i = 0; i < myCount; i++) {
        for (int c = 0; c < T; c++) {
            int j = i * T + c;
            if (j + 1 < myTotal) {
                asm volatile("cp.async.wait_group 1;" ::: "memory");
            } else {
                asm volatile("cp.async.wait_group 0;" ::: "memory");
            }
            __syncthreads();

            prefetchChunk(j + 2);

            unsigned aB = sbase + (unsigned)(j % 3) * STG;
            unsigned bB = aB + 16384u;

            unsigned afrag[2][4][4], bfrag[2][4][4];
            #pragma unroll
            for (int mi = 0; mi < 4; mi++)
                ldsm4(afrag[0][mi], aB + swz(wm * 64 + mi * 16 + lrow16, lhalf));
            #pragma unroll
            for (int p = 0; p < 4; p++)
                ldsm4(bfrag[0][p], bB + swz(wn * 64 + p * 16 + lrow16, lhalf));

            #pragma unroll
            for (int ks = 0; ks < 4; ks++) {
                int cur = ks & 1, nxt = cur ^ 1;
                if (ks < 3) {
                    #pragma unroll
                    for (int mi = 0; mi < 4; mi++)
                        ldsm4(afrag[nxt][mi], aB + swz(wm * 64 + mi * 16 + lrow16, (ks + 1) * 2 + lhalf));
                    #pragma unroll
                    for (int p = 0; p < 4; p++)
                        ldsm4(bfrag[nxt][p], bB + swz(wn * 64 + p * 16 + lrow16, (ks + 1) * 2 + lhalf));
                }
                #pragma unroll
                for (int mi = 0; mi < 4; mi++) {
                    #pragma unroll
                    for (int ni = 0; ni < 8; ni++) {
                        const unsigned* bf = bfrag[cur][ni >> 1];
                        if (IN8) mma_e4m3(acc[mi][ni], afrag[cur][mi], bf[ni & 1], bf[2 + (ni & 1)]);
                        else     mma_bf16(acc[mi][ni], afrag[cur][mi], bf[ni & 1], bf[2 + (ni & 1)]);
                    }
                }
            }
        }

        // ---------------- epilogue ----------------
        {
            int p = (int)blockIdx.x + i * G;
            int lt = SPLITK ? (p >> 1) : p;
            int hk = SPLITK ? (p & 1) : 0;
            int z = lt / gxy; int rr = lt - z * gxy;
            int by = rr / gx, bx = rr - by * gx;
            int m0 = by * 128, n0 = bx * 256;
            const int g = lane >> 2, tig = lane & 3;

            const float* oscr = nullptr;
            bool emit = true;
            if (SPLITK) {
                float* scr = scratch + ((long long)(hk * ntL + lt) << 15);
                #pragma unroll
                for (int mi = 0; mi < 4; mi++) {
                    #pragma unroll
                    for (int half = 0; half < 2; half++) {
                        int tr = wm * 64 + mi * 16 + g + half * 8;
                        #pragma unroll
                        for (int ni = 0; ni < 8; ni++) {
                            int tc = wn * 64 + ni * 8 + tig * 2;
                            *(float2*)(scr + tr * 256 + tc) =
                                make_float2(acc[mi][ni][half * 2], acc[mi][ni][half * 2 + 1]);
                        }
                    }
                }
                __threadfence();
                __syncthreads();
                if (t == 0) sOld = atomicAdd(ctr + lt, 1);
                __syncthreads();
                emit = (sOld == 1);
                if (emit) oscr = scratch + ((long long)((hk ^ 1) * ntL + lt) << 15);
            }

            if (emit) {
                #pragma unroll
                for (int mi = 0; mi < 4; mi++) {
                    #pragma unroll
                    for (int half = 0; half < 2; half++) {
                        int row = m0 + wm * 64 + mi * 16 + g + half * 8;
                        int tr = wm * 64 + mi * 16 + g + half * 8;
                        float rs = 0.0f;
                        if (EPI == 4) rs = 1.0f / dptr[z * sRS + row];
                        float rsum = 0.0f;
                        #pragma unroll
                        for (int ni = 0; ni < 8; ni++) {
                            int tc = wn * 64 + ni * 8 + tig * 2;
                            int col = n0 + tc;
                            float v0 = acc[mi][ni][half * 2];
                            float v1 = acc[mi][ni][half * 2 + 1];
                            if (SPLITK) {
                                float2 ov = *(const float2*)(oscr + tr * 256 + tc);
                                v0 += ov.x; v1 += ov.y;
                            }
                            if (EPI == 1) { v0 += bias[col]; v1 += bias[col + 1]; }
                            if (EPI == 2) { v0 = exp2f(v0 * alpha); v1 = exp2f(v1 * alpha); rsum += v0 + v1; }
                            if (EPI == 4) {
                                const float* rp = resid + z * sR + (long long)row * ldc + col;
                                v0 = v0 * rs + bias[col] + rp[0];
                                v1 = v1 * rs + bias[col + 1] + rp[1];
                                float* C = (float*)Cv + z * sC;
                                *(float2*)(C + (long long)row * ldc + col) = make_float2(v0, v1);
                            } else {
                                __nv_bfloat16* C = (__nv_bfloat16*)Cv + z * sC;
                                __nv_bfloat162 pv = {__float2bfloat16(v0), __float2bfloat16(v1)};
                                *(__nv_bfloat162*)(C + (long long)row * ldc + col) = pv;
                            }
                        }
                        if (EPI == 2) {
                            rsum += __shfl_xor_sync(0xffffffffu, rsum, 1);
                            rsum += __shfl_xor_sync(0xffffffffu, rsum, 2);
                            if (tig == 0) atomicAdd(dptr + z * sRS + row, rsum);
                        }
                    }
                }
            }
        }
        #pragma unroll
        for (int a = 0; a < 4; a++)
            #pragma unroll
            for (int b = 0; b < 8; b++)
                #pragma unroll
                for (int v = 0; v < 4; v++) acc[a][b][v] = 0.0f;
    }
}

// ---------------- launch ----------------
extern "C" void kernel_launch(void* const* d_in, const int* in_sizes, int n_in,
                              void* d_out, int out_size) {
    const float* x      = (const float*)d_in[0];
    const float* g_norm = (const float*)d_in[1];
    const float* w_qkv  = (const float*)d_in[2];
    const float* b_qkv  = (const float*)d_in[3];
    const float* w_proj = (const float*)d_in[4];
    const float* b_proj = (const float*)d_in[5];
    float* out = (float*)d_out;

    void *pqkv, *pP, *ph, *pq, *pk, *pvw, *pwq, *pwp, *pd, *psc, *pct;
    cudaGetSymbolAddress(&pqkv, g_qkvbf);
    cudaGetSymbolAddress(&pP, g_P);
    cudaGetSymbolAddress(&ph, g_hbf);
    cudaGetSymbolAddress(&pq, g_qf8);
    cudaGetSymbolAddress(&pk, g_kf8);
    cudaGetSymbolAddress(&pvw, g_vwT);
    cudaGetSymbolAddress(&pwq, g_wqkvT);
    cudaGetSymbolAddress(&pwp, g_wprojT);
    cudaGetSymbolAddress(&pd, g_den);
    cudaGetSymbolAddress(&psc, g_scratch);
    cudaGetSymbolAddress(&pct, g_ctr);
    __nv_bfloat16* qkvbf = (__nv_bfloat16*)pqkv;
    __nv_bfloat16* P     = (__nv_bfloat16*)pP;
    __nv_bfloat16* hbf   = (__nv_bfloat16*)ph;
    unsigned char* qf8   = (unsigned char*)pq;
    unsigned char* kf8   = (unsigned char*)pk;
    __nv_bfloat16* vwT   = (__nv_bfloat16*)pvw;
    __nv_bfloat16* wqkvT = (__nv_bfloat16*)pwq;
    __nv_bfloat16* wprojT= (__nv_bfloat16*)pwp;
    float* den           = (float*)pd;
    float* scratch       = (float*)psc;
    int*   ctr           = (int*)pct;

    int sm = 148;
    cudaDeviceGetAttribute(&sm, cudaDevAttrMultiProcessorCount, 0);

    const int SMEM = 3 * (int)STG;   // 144KB
    cudaFuncSetAttribute(gemm_tc<0,1,0>, cudaFuncAttributeMaxDynamicSharedMemorySize, SMEM);
    cudaFuncSetAttribute(gemm_tc<1,2,0>, cudaFuncAttributeMaxDynamicSharedMemorySize, SMEM);
    cudaFuncSetAttribute(gemm_tc<0,3,1>, cudaFuncAttributeMaxDynamicSharedMemorySize, SMEM);
    cudaFuncSetAttribute(gemm_tc<0,4,1>, cudaFuncAttributeMaxDynamicSharedMemorySize, SMEM);

    // 1) tables + weight transposes + rmsnorm + zero den/counters
    build_inv_kernel<<<1, HALF>>>();
    build_tables_kernel<<<(SS * HALF + 255) / 256, 256>>>();
    transpose_cvt_kernel<<<dim3(TD / 32, DD / 32), 256>>>(w_qkv, TD, wqkvT, DD);
    transpose_cvt_kernel<<<dim3(DD / 32, DD / 32), 256>>>(w_proj, DD, wprojT, DD);
    rmsnorm_kernel<<<BB * SS, 256>>>(x, g_norm, hbf);
    zero_kernel<<<(BB * SS + 1024 + 255) / 256, 256>>>(den, ctr);

    // 2) qkv = h @ w_qkv + b_qkv  -> bf16   (M=16384,N=3072,K=1024)
    {
        int gx = TD / 256, gy = (BB * SS) / 128, gz = 1;
        int nt = gx * gy * gz, G = nt < sm ? nt : sm;
        gemm_tc<0,1,0><<<G, 256, SMEM>>>(
            DD * 2 / 128, gx, gy, gz,
            (const char*)hbf, DD * 2, 0LL,
            (const char*)wqkvT, DD * 2, 0LL,
            qkvbf, TD, 0LL,
            1.0f, b_qkv, nullptr, 0LL, nullptr, 0LL, nullptr, nullptr);
    }

    // 3) rope -> q,k fp8 ; vwT = wprojT @ V^T  (split-K=2; M=1024,N=4096,K=1024 per batch)
    rope_kernel<<<BB * SS, 256>>>(qkvbf, (unsigned short*)qf8, (unsigned short*)kf8);
    {
        int gx = SS / 256, gy = DD / 128, gz = BB;
        int nt = 2 * gx * gy * gz, G = nt < sm ? nt : sm;
        gemm_tc<0,3,1><<<G, 256, SMEM>>>(
            DD * 2 / 128 / 2, gx, gy, gz,
            (const char*)wprojT, DD * 2, 0LL,
            (const char*)(qkvbf + 2 * DD), (long long)TD * 2, (long long)SS * TD * 2,
            vwT, SS, (long long)DD * SS,
            1.0f, nullptr, nullptr, 0LL, nullptr, 0LL, scratch, ctr);
    }

    // 4) P = 3^(q@k^T / 32) -> bf16, fused row-sum atomics into den  (M=N=4096,K=1024 fp8)
    {
        int gx = SS / 256, gy = SS / 128, gz = BB;
        int nt = gx * gy * gz, G = nt < sm ? nt : sm;
        gemm_tc<1,2,0><<<G, 256, SMEM>>>(
            DD / 128, gx, gy, gz,
            (const char*)qf8, DD, (long long)SS * DD,
            (const char*)kf8, DD, (long long)SS * DD,
            P, SS, (long long)SS * SS,
            1.5849625007211562f / 32.0f, nullptr, nullptr, 0LL, den, (long long)SS, nullptr, nullptr);
    }

    // 5) out = (P @ vwT^T)/den + b_proj + x  -> f32 (split-K=2; M=4096,N=1024,K=4096 per batch)
    {
        int gx = DD / 256, gy = SS / 128, gz = BB;
        int nt = 2 * gx * gy * gz, G = nt < sm ? nt : sm;
        gemm_tc<0,4,1><<<G, 256, SMEM>>>(
            SS * 2 / 128 / 2, gx, gy, gz,
            (const char*)P, (long long)SS * 2, (long long)SS * SS * 2,
            (const char*)vwT, (long long)SS * 2, (long long)DD * SS * 2,
            out, DD, (long long)SS * DD,
            1.0f, b_proj, x, (long long)SS * DD, den, (long long)SS, scratch, ctr + 512);
    }
}